// round 4
// baseline (speedup 1.0000x reference)
#include <cuda_runtime.h>

#define B_ 4
#define C_ 64
#define H_ 64
#define W_ 192
#define D_ 24
#define HW_ (H_*W_)

// Feature maps [vol][b][h*w][c] (channel-contiguous per pixel).
__device__ float g_Q[2][B_][HW_][C_];
__device__ float g_K[2][B_][HW_][C_];
// Transposed weights: g_wt[m][cin][cout]
__device__ float g_wt[2][C_][C_];

typedef unsigned long long u64;

__device__ __forceinline__ u64 pack2(float x) {
    unsigned r = __float_as_uint(x);
    u64 p;
    asm("mov.b64 %0, {%1, %1};" : "=l"(p) : "r"(r));
    return p;
}
__device__ __forceinline__ u64 ffma2(u64 a, u64 b, u64 c) {
    u64 d;
    asm("fma.rn.f32x2 %0, %1, %2, %3;" : "=l"(d) : "l"(a), "l"(b), "l"(c));
    return d;
}
__device__ __forceinline__ float2 unpack2(u64 p) {
    unsigned lo, hi;
    asm("mov.b64 {%0, %1}, %2;" : "=r"(lo), "=r"(hi) : "l"(p));
    return make_float2(__uint_as_float(lo), __uint_as_float(hi));
}

// ---------------------------------------------------------------------------
// Prep: transpose weights into g_wt[m][cin][cout].
// ---------------------------------------------------------------------------
__global__ void prep_kernel(const float* __restrict__ qw,
                            const float* __restrict__ kw) {
    const int m = blockIdx.x;
    const float* w = m ? kw : qw;
    for (int e = threadIdx.x; e < 4096; e += 256) {
        int o = e >> 6, i = e & 63;        // coalesced read over i
        g_wt[m][i][o] = w[o * 64 + i];
    }
}

// ---------------------------------------------------------------------------
// Conv1x1, zero shared memory. Block=(h,b,src), 256 thr, 4 CTAs/SM (regs).
// Thread tile: 4 cout x 6 pix (f32x2 over pixel pairs). A from L1-hot g_wt,
// B directly from the input row (L1-hot after first touch).
// ---------------------------------------------------------------------------
__global__ __launch_bounds__(256, 4) void conv1x1_kernel(
    const float* __restrict__ x, const float* __restrict__ y,
    const float* __restrict__ qb, const float* __restrict__ kb)
{
    const int h = blockIdx.x, b = blockIdx.y, srcIdx = blockIdx.z;
    const float* src = (srcIdx == 0) ? x : y;
    const int tid = threadIdx.x;
    const int tc = tid >> 4;   // 0..15 -> cout base tc*4
    const int tx = tid & 15;   // 0..15 -> pix  base tx*6 (within 96-half)

    #pragma unroll 1
    for (int pass = 0; pass < 2; ++pass) {
        const int pixb = pass * 96 + tx * 6;
        const float* inrow = src + (size_t)b * 64 * HW_ + h * 192 + pixb;

        #pragma unroll 1
        for (int m = 0; m < 2; ++m) {
            u64 acc[4][3];
            #pragma unroll
            for (int i = 0; i < 4; i++)
                #pragma unroll
                for (int j = 0; j < 3; j++) acc[i][j] = 0ull;

            const float* A = &g_wt[m][0][tc * 4];
            #pragma unroll 4
            for (int k = 0; k < 64; ++k) {
                u64 b0 = *(const u64*)(inrow + k * HW_);
                u64 b1 = *(const u64*)(inrow + k * HW_ + 2);
                u64 b2 = *(const u64*)(inrow + k * HW_ + 4);
                float4 av = *(const float4*)(A + k * 64);
                u64 ap[4] = {pack2(av.x), pack2(av.y), pack2(av.z), pack2(av.w)};
                #pragma unroll
                for (int i = 0; i < 4; i++) {
                    acc[i][0] = ffma2(ap[i], b0, acc[i][0]);
                    acc[i][1] = ffma2(ap[i], b1, acc[i][1]);
                    acc[i][2] = ffma2(ap[i], b2, acc[i][2]);
                }
            }

            const float* bias = m ? kb : qb;
            float4 bz = *(const float4*)&bias[tc * 4];
            float* outp = (m == 0) ? &g_Q[srcIdx][b][h * W_][0]
                                   : &g_K[srcIdx ^ 1][b][h * W_][0];
            #pragma unroll
            for (int j = 0; j < 3; j++) {
                float2 t0 = unpack2(acc[0][j]), t1 = unpack2(acc[1][j]);
                float2 t2 = unpack2(acc[2][j]), t3 = unpack2(acc[3][j]);
                float* o0 = outp + (size_t)(pixb + 2 * j) * 64 + tc * 4;
                *(float4*)o0 = make_float4(t0.x + bz.x, t1.x + bz.y,
                                           t2.x + bz.z, t3.x + bz.w);
                *(float4*)(o0 + 64) = make_float4(t0.y + bz.x, t1.y + bz.y,
                                                  t2.y + bz.z, t3.y + bz.w);
            }
        }
    }
}

// ---------------------------------------------------------------------------
// Cost volume (direct gather). Block=(h,b,vol), 256 thr, 4 CTAs/SM ->
// single wave (592 >= 512). f32x2 blend+dot. Disp pipelined 6-deep.
// ---------------------------------------------------------------------------
__global__ __launch_bounds__(256, 4) void cost_kernel(
    const float* __restrict__ d1, const float* __restrict__ d2,
    float* __restrict__ out)
{
    __shared__ float kb_s[W_][C_];     // 48 KB
    const int h = blockIdx.x, b = blockIdx.y, vol = blockIdx.z;
    const int tid = threadIdx.x;

    float ys  = h * (64.0f / 63.0f) - 0.5f;
    float y0f = floorf(ys);
    float ty  = ys - y0f;
    int iy0 = (int)y0f, iy1 = iy0 + 1;
    float wy0 = (iy0 >= 0 && iy0 < H_) ? (1.0f - ty) : 0.0f;
    float wy1 = (iy1 >= 0 && iy1 < H_) ? ty : 0.0f;
    int y0c = min(max(iy0, 0), H_ - 1);
    int y1c = min(max(iy1, 0), H_ - 1);
    const float4* k0 = (const float4*)&g_K[vol][b][y0c * W_][0];
    const float4* k1 = (const float4*)&g_K[vol][b][y1c * W_][0];
    float4* kb4 = (float4*)&kb_s[0][0];
    #pragma unroll
    for (int e = tid; e < 3072; e += 256) {
        float4 a = k0[e], c = k1[e];
        kb4[e] = make_float4(wy0 * a.x + wy1 * c.x, wy0 * a.y + wy1 * c.y,
                             wy0 * a.z + wy1 * c.z, wy0 * a.w + wy1 * c.w);
    }
    __syncthreads();

    const int warp = tid >> 5, lane = tid & 31;
    const int wsub = lane >> 3, cg = lane & 7;
    const float* dispb = ((vol == 0) ? d1 : d2) + (size_t)b * D_ * HW_ + h * W_;
    float* outb = out + ((size_t)(vol * B_ + b) * D_) * HW_ + h * W_;

    #pragma unroll 1
    for (int pass = 0; pass < 6; ++pass) {
        const int w = pass * 32 + warp * 4 + wsub;
        const float* qp = &g_Q[vol][b][h * W_ + w][0];
        float4 qAv = *(const float4*)(qp + cg * 4);
        float4 qBv = *(const float4*)(qp + 32 + cg * 4);
        u64 qa0 = ((u64*)&qAv)[0], qa1 = ((u64*)&qAv)[1];
        u64 qb0 = ((u64*)&qBv)[0], qb1 = ((u64*)&qBv)[1];
        const float* dp = dispb + w;

        float cur[6];
        #pragma unroll
        for (int j = 0; j < 6; j++) cur[j] = __ldg(dp + j * HW_);

        #pragma unroll 1
        for (int chunk = 0; chunk < 4; ++chunk) {
            float nxt[6];
            if (chunk < 3) {
                #pragma unroll
                for (int j = 0; j < 6; j++)
                    nxt[j] = __ldg(dp + (chunk * 6 + 6 + j) * HW_);
            }
            #pragma unroll
            for (int j = 0; j < 6; j++) {
                const int d = chunk * 6 + j;
                float xs  = cur[j] * (192.0f / 191.0f) - 0.5f;
                float x0f = floorf(xs);
                float txf = xs - x0f;
                int ix0 = (int)x0f;
                float wx0 = (ix0 >= 0 && ix0 < W_) ? (1.0f - txf) : 0.0f;
                float wx1 = (ix0 + 1 >= 0 && ix0 + 1 < W_) ? txf : 0.0f;
                int x0c = min(max(ix0, 0), W_ - 1);
                int x1c = min(max(ix0 + 1, 0), W_ - 1);
                const float* r0 = &kb_s[x0c][0];
                const float* r1 = &kb_s[x1c][0];
                float4 a0 = *(const float4*)(r0 + cg * 4);
                float4 b0 = *(const float4*)(r0 + 32 + cg * 4);
                float4 a1 = *(const float4*)(r1 + cg * 4);
                float4 b1 = *(const float4*)(r1 + 32 + cg * 4);

                u64 w0 = pack2(wx0), w1 = pack2(wx1);
                u64 t, acc = 0ull;
                t = ffma2(w1, ((u64*)&a1)[0], 0ull);
                t = ffma2(w0, ((u64*)&a0)[0], t);
                acc = ffma2(qa0, t, acc);
                t = ffma2(w1, ((u64*)&a1)[1], 0ull);
                t = ffma2(w0, ((u64*)&a0)[1], t);
                acc = ffma2(qa1, t, acc);
                t = ffma2(w1, ((u64*)&b1)[0], 0ull);
                t = ffma2(w0, ((u64*)&b0)[0], t);
                acc = ffma2(qb0, t, acc);
                t = ffma2(w1, ((u64*)&b1)[1], 0ull);
                t = ffma2(w0, ((u64*)&b0)[1], t);
                acc = ffma2(qb1, t, acc);

                float2 f = unpack2(acc);
                float s = f.x + f.y;
                s += __shfl_xor_sync(0xffffffffu, s, 1);
                s += __shfl_xor_sync(0xffffffffu, s, 2);
                s += __shfl_xor_sync(0xffffffffu, s, 4);
                if (cg == 0) outb[d * HW_ + w] = s * 0.015625f;
            }
            if (chunk < 3) {
                #pragma unroll
                for (int j = 0; j < 6; j++) cur[j] = nxt[j];
            }
        }
    }
}

extern "C" void kernel_launch(void* const* d_in, const int* in_sizes, int n_in,
                              void* d_out, int out_size) {
    const float* x  = (const float*)d_in[0];
    const float* y  = (const float*)d_in[1];
    const float* d1 = (const float*)d_in[2];
    const float* d2 = (const float*)d_in[3];
    int wbase = (in_sizes[4] == 1) ? 5 : 4;
    const float* qw = (const float*)d_in[wbase + 0];
    const float* qb = (const float*)d_in[wbase + 1];
    const float* kw = (const float*)d_in[wbase + 2];
    const float* kb = (const float*)d_in[wbase + 3];
    float* out = (float*)d_out;

    prep_kernel<<<2, 256>>>(qw, kw);
    conv1x1_kernel<<<dim3(H_, B_, 2), 256>>>(x, y, qb, kb);
    cost_kernel<<<dim3(H_, B_, 2), 256>>>(d1, d2, out);
}

// round 5
// speedup vs baseline: 1.2606x; 1.2606x over previous
#include <cuda_runtime.h>

#define B_ 4
#define C_ 64
#define H_ 64
#define W_ 192
#define D_ 24
#define HW_ (H_*W_)

// Feature maps [vol][b][h*w][c] (channel-contiguous per pixel).
__device__ float g_Q[2][B_][HW_][C_];
__device__ float g_K[2][B_][HW_][C_];

typedef unsigned long long u64;

__device__ __forceinline__ u64 pack2(float x) {
    unsigned r = __float_as_uint(x);
    u64 p;
    asm("mov.b64 %0, {%1, %1};" : "=l"(p) : "r"(r));
    return p;
}
__device__ __forceinline__ u64 ffma2(u64 a, u64 b, u64 c) {
    u64 d;
    asm("fma.rn.f32x2 %0, %1, %2, %3;" : "=l"(d) : "l"(a), "l"(b), "l"(c));
    return d;
}
__device__ __forceinline__ float2 unpack2(u64 p) {
    unsigned lo, hi;
    asm("mov.b64 {%0, %1}, %2;" : "=r"(lo), "=r"(hi) : "l"(p));
    return make_float2(__uint_as_float(lo), __uint_as_float(hi));
}

// ---------------------------------------------------------------------------
// Conv1x1. Block = half image row (96 pix), 56 KB smem, 4 CTAs/SM.
// Warp = 8 couts, lane = 3 pixels. FFMA2 packed over cout pairs.
// ---------------------------------------------------------------------------
__global__ __launch_bounds__(256, 4) void conv1x1_kernel(
    const float* __restrict__ x, const float* __restrict__ y,
    const float* __restrict__ qw, const float* __restrict__ qb,
    const float* __restrict__ kw, const float* __restrict__ kb)
{
    __shared__ float in_s[64][96];       // 24 KB
    __shared__ float wt_s[2][64][64];    // 32 KB, [m][cin][cout]
    const int h = blockIdx.x >> 1, half = blockIdx.x & 1;
    const int b = blockIdx.y, srcIdx = blockIdx.z;
    const float* src = (srcIdx == 0) ? x : y;
    const int tid = threadIdx.x;

    // Stage input half-row (coalesced float4 per channel).
    const float* srow = src + (size_t)b * 64 * HW_ + h * 192 + half * 96;
    #pragma unroll
    for (int e4 = tid; e4 < 1536; e4 += 256) {
        int k = e4 / 24, w4 = e4 - k * 24;
        *(float4*)&in_s[k][w4 * 4] = *(const float4*)(srow + (size_t)k * HW_ + w4 * 4);
    }
    // Stage transposed weights, conflict-free stores (lane -> distinct cout).
    #pragma unroll
    for (int e4 = tid; e4 < 2048; e4 += 256) {
        int m = e4 >> 10, idx = e4 & 1023;
        int o = idx & 63, i4 = idx >> 6;             // i4: 0..15
        const float* w = m ? kw : qw;
        float4 v = *(const float4*)(w + o * 64 + i4 * 4);
        wt_s[m][i4 * 4 + 0][o] = v.x;
        wt_s[m][i4 * 4 + 1][o] = v.y;
        wt_s[m][i4 * 4 + 2][o] = v.z;
        wt_s[m][i4 * 4 + 3][o] = v.w;
    }
    __syncthreads();

    const int tw = tid >> 5;        // warp -> cout base tw*8
    const int lp = (tid & 31) * 3;  // lane -> 3 pixels

    #pragma unroll 1
    for (int m = 0; m < 2; ++m) {
        u64 acc[4][3];
        #pragma unroll
        for (int i = 0; i < 4; i++)
            #pragma unroll
            for (int j = 0; j < 3; j++) acc[i][j] = 0ull;

        #pragma unroll 4
        for (int k = 0; k < 64; ++k) {
            float4 a0 = *(const float4*)&wt_s[m][k][tw * 8];      // uniform
            float4 a1 = *(const float4*)&wt_s[m][k][tw * 8 + 4];  // uniform
            u64 ap[4];
            ap[0] = ((u64*)&a0)[0]; ap[1] = ((u64*)&a0)[1];
            ap[2] = ((u64*)&a1)[0]; ap[3] = ((u64*)&a1)[1];
            u64 bp[3];
            bp[0] = pack2(in_s[k][lp]);
            bp[1] = pack2(in_s[k][lp + 1]);
            bp[2] = pack2(in_s[k][lp + 2]);
            #pragma unroll
            for (int i = 0; i < 4; i++)
                #pragma unroll
                for (int j = 0; j < 3; j++)
                    acc[i][j] = ffma2(ap[i], bp[j], acc[i][j]);
        }

        const float* bias = m ? kb : qb;
        float4 bz0 = *(const float4*)&bias[tw * 8];
        float4 bz1 = *(const float4*)&bias[tw * 8 + 4];
        float* outp = (m == 0) ? &g_Q[srcIdx][b][h * W_ + half * 96][0]
                               : &g_K[srcIdx ^ 1][b][h * W_ + half * 96][0];
        #pragma unroll
        for (int j = 0; j < 3; j++) {
            float2 t0 = unpack2(acc[0][j]), t1 = unpack2(acc[1][j]);
            float2 t2 = unpack2(acc[2][j]), t3 = unpack2(acc[3][j]);
            float* op = outp + (size_t)(lp + j) * 64 + tw * 8;
            *(float4*)op = make_float4(t0.x + bz0.x, t0.y + bz0.y,
                                       t1.x + bz0.z, t1.y + bz0.w);
            *(float4*)(op + 4) = make_float4(t2.x + bz1.x, t2.y + bz1.y,
                                             t3.x + bz1.z, t3.y + bz1.w);
        }
    }
}

// ---------------------------------------------------------------------------
// Cost volume (direct gather). Block=(h,b,vol), 256 thr, 4 CTAs/SM.
// f32x2 blend+dot. Disp pipelined 6-deep.
// ---------------------------------------------------------------------------
__global__ __launch_bounds__(256, 4) void cost_kernel(
    const float* __restrict__ d1, const float* __restrict__ d2,
    float* __restrict__ out)
{
    __shared__ float kb_s[W_][C_];     // 48 KB
    const int h = blockIdx.x, b = blockIdx.y, vol = blockIdx.z;
    const int tid = threadIdx.x;

    float ys  = h * (64.0f / 63.0f) - 0.5f;
    float y0f = floorf(ys);
    float ty  = ys - y0f;
    int iy0 = (int)y0f, iy1 = iy0 + 1;
    float wy0 = (iy0 >= 0 && iy0 < H_) ? (1.0f - ty) : 0.0f;
    float wy1 = (iy1 >= 0 && iy1 < H_) ? ty : 0.0f;
    int y0c = min(max(iy0, 0), H_ - 1);
    int y1c = min(max(iy1, 0), H_ - 1);
    const float4* k0 = (const float4*)&g_K[vol][b][y0c * W_][0];
    const float4* k1 = (const float4*)&g_K[vol][b][y1c * W_][0];
    float4* kb4 = (float4*)&kb_s[0][0];
    #pragma unroll
    for (int e = tid; e < 3072; e += 256) {
        float4 a = k0[e], c = k1[e];
        kb4[e] = make_float4(wy0 * a.x + wy1 * c.x, wy0 * a.y + wy1 * c.y,
                             wy0 * a.z + wy1 * c.z, wy0 * a.w + wy1 * c.w);
    }
    __syncthreads();

    const int warp = tid >> 5, lane = tid & 31;
    const int wsub = lane >> 3, cg = lane & 7;
    const float* dispb = ((vol == 0) ? d1 : d2) + (size_t)b * D_ * HW_ + h * W_;
    float* outb = out + ((size_t)(vol * B_ + b) * D_) * HW_ + h * W_;

    #pragma unroll 1
    for (int pass = 0; pass < 6; ++pass) {
        const int w = pass * 32 + warp * 4 + wsub;
        const float* qp = &g_Q[vol][b][h * W_ + w][0];
        float4 qAv = *(const float4*)(qp + cg * 4);
        float4 qBv = *(const float4*)(qp + 32 + cg * 4);
        u64 qa0 = ((u64*)&qAv)[0], qa1 = ((u64*)&qAv)[1];
        u64 qb0 = ((u64*)&qBv)[0], qb1 = ((u64*)&qBv)[1];
        const float* dp = dispb + w;

        float cur[6];
        #pragma unroll
        for (int j = 0; j < 6; j++) cur[j] = __ldg(dp + j * HW_);

        #pragma unroll 1
        for (int chunk = 0; chunk < 4; ++chunk) {
            float nxt[6];
            if (chunk < 3) {
                #pragma unroll
                for (int j = 0; j < 6; j++)
                    nxt[j] = __ldg(dp + (chunk * 6 + 6 + j) * HW_);
            }
            #pragma unroll
            for (int j = 0; j < 6; j++) {
                const int d = chunk * 6 + j;
                float xs  = cur[j] * (192.0f / 191.0f) - 0.5f;
                float x0f = floorf(xs);
                float txf = xs - x0f;
                int ix0 = (int)x0f;
                float wx0 = (ix0 >= 0 && ix0 < W_) ? (1.0f - txf) : 0.0f;
                float wx1 = (ix0 + 1 >= 0 && ix0 + 1 < W_) ? txf : 0.0f;
                int x0c = min(max(ix0, 0), W_ - 1);
                int x1c = min(max(ix0 + 1, 0), W_ - 1);
                const float* r0 = &kb_s[x0c][0];
                const float* r1 = &kb_s[x1c][0];
                float4 a0 = *(const float4*)(r0 + cg * 4);
                float4 b0 = *(const float4*)(r0 + 32 + cg * 4);
                float4 a1 = *(const float4*)(r1 + cg * 4);
                float4 b1 = *(const float4*)(r1 + 32 + cg * 4);

                u64 w0 = pack2(wx0), w1 = pack2(wx1);
                u64 t, acc = 0ull;
                t = ffma2(w1, ((u64*)&a1)[0], 0ull);
                t = ffma2(w0, ((u64*)&a0)[0], t);
                acc = ffma2(qa0, t, acc);
                t = ffma2(w1, ((u64*)&a1)[1], 0ull);
                t = ffma2(w0, ((u64*)&a0)[1], t);
                acc = ffma2(qa1, t, acc);
                t = ffma2(w1, ((u64*)&b1)[0], 0ull);
                t = ffma2(w0, ((u64*)&b0)[0], t);
                acc = ffma2(qb0, t, acc);
                t = ffma2(w1, ((u64*)&b1)[1], 0ull);
                t = ffma2(w0, ((u64*)&b0)[1], t);
                acc = ffma2(qb1, t, acc);

                float2 f = unpack2(acc);
                float s = f.x + f.y;
                s += __shfl_xor_sync(0xffffffffu, s, 1);
                s += __shfl_xor_sync(0xffffffffu, s, 2);
                s += __shfl_xor_sync(0xffffffffu, s, 4);
                if (cg == 0) outb[d * HW_ + w] = s * 0.015625f;
            }
            if (chunk < 3) {
                #pragma unroll
                for (int j = 0; j < 6; j++) cur[j] = nxt[j];
            }
        }
    }
}

extern "C" void kernel_launch(void* const* d_in, const int* in_sizes, int n_in,
                              void* d_out, int out_size) {
    const float* x  = (const float*)d_in[0];
    const float* y  = (const float*)d_in[1];
    const float* d1 = (const float*)d_in[2];
    const float* d2 = (const float*)d_in[3];
    int wbase = (in_sizes[4] == 1) ? 5 : 4;
    const float* qw = (const float*)d_in[wbase + 0];
    const float* qb = (const float*)d_in[wbase + 1];
    const float* kw = (const float*)d_in[wbase + 2];
    const float* kb = (const float*)d_in[wbase + 3];
    float* out = (float*)d_out;

    conv1x1_kernel<<<dim3(128, B_, 2), 256>>>(x, y, qw, qb, kw, kb);
    cost_kernel<<<dim3(H_, B_, 2), 256>>>(d1, d2, out);
}

// round 6
// speedup vs baseline: 1.4358x; 1.1391x over previous
#include <cuda_runtime.h>

#define B_ 4
#define C_ 64
#define H_ 64
#define W_ 192
#define D_ 24
#define HW_ (H_*W_)

// Feature maps [vol][b][h*w][c] (channel-contiguous per pixel).
__device__ float g_Q[2][B_][HW_][C_];
__device__ float g_K[2][B_][HW_][C_];

typedef unsigned long long u64;

__device__ __forceinline__ u64 pack2(float x) {
    unsigned r = __float_as_uint(x);
    u64 p;
    asm("mov.b64 %0, {%1, %1};" : "=l"(p) : "r"(r));
    return p;
}
__device__ __forceinline__ u64 ffma2(u64 a, u64 b, u64 c) {
    u64 d;
    asm("fma.rn.f32x2 %0, %1, %2, %3;" : "=l"(d) : "l"(a), "l"(b), "l"(c));
    return d;
}
__device__ __forceinline__ float2 unpack2(u64 p) {
    unsigned lo, hi;
    asm("mov.b64 {%0, %1}, %2;" : "=r"(lo), "=r"(hi) : "l"(p));
    return make_float2(__uint_as_float(lo), __uint_as_float(hi));
}
__device__ __forceinline__ unsigned to_tf32(float f) {
    unsigned u;
    asm("cvt.rna.tf32.f32 %0, %1;" : "=r"(u) : "f"(f));
    return u;
}

// ---------------------------------------------------------------------------
// Conv1x1 (unchanged from R5). Block = half image row, 56 KB smem.
// ---------------------------------------------------------------------------
__global__ __launch_bounds__(256, 4) void conv1x1_kernel(
    const float* __restrict__ x, const float* __restrict__ y,
    const float* __restrict__ qw, const float* __restrict__ qb,
    const float* __restrict__ kw, const float* __restrict__ kb)
{
    __shared__ float in_s[64][96];
    __shared__ float wt_s[2][64][64];
    const int h = blockIdx.x >> 1, half = blockIdx.x & 1;
    const int b = blockIdx.y, srcIdx = blockIdx.z;
    const float* src = (srcIdx == 0) ? x : y;
    const int tid = threadIdx.x;

    const float* srow = src + (size_t)b * 64 * HW_ + h * 192 + half * 96;
    #pragma unroll
    for (int e4 = tid; e4 < 1536; e4 += 256) {
        int k = e4 / 24, w4 = e4 - k * 24;
        *(float4*)&in_s[k][w4 * 4] = *(const float4*)(srow + (size_t)k * HW_ + w4 * 4);
    }
    #pragma unroll
    for (int e4 = tid; e4 < 2048; e4 += 256) {
        int m = e4 >> 10, idx = e4 & 1023;
        int o = idx & 63, i4 = idx >> 6;
        const float* w = m ? kw : qw;
        float4 v = *(const float4*)(w + o * 64 + i4 * 4);
        wt_s[m][i4 * 4 + 0][o] = v.x;
        wt_s[m][i4 * 4 + 1][o] = v.y;
        wt_s[m][i4 * 4 + 2][o] = v.z;
        wt_s[m][i4 * 4 + 3][o] = v.w;
    }
    __syncthreads();

    const int tw = tid >> 5;
    const int lp = (tid & 31) * 3;

    #pragma unroll 1
    for (int m = 0; m < 2; ++m) {
        u64 acc[4][3];
        #pragma unroll
        for (int i = 0; i < 4; i++)
            #pragma unroll
            for (int j = 0; j < 3; j++) acc[i][j] = 0ull;

        #pragma unroll 4
        for (int k = 0; k < 64; ++k) {
            float4 a0 = *(const float4*)&wt_s[m][k][tw * 8];
            float4 a1 = *(const float4*)&wt_s[m][k][tw * 8 + 4];
            u64 ap[4];
            ap[0] = ((u64*)&a0)[0]; ap[1] = ((u64*)&a0)[1];
            ap[2] = ((u64*)&a1)[0]; ap[3] = ((u64*)&a1)[1];
            u64 bp[3];
            bp[0] = pack2(in_s[k][lp]);
            bp[1] = pack2(in_s[k][lp + 1]);
            bp[2] = pack2(in_s[k][lp + 2]);
            #pragma unroll
            for (int i = 0; i < 4; i++)
                #pragma unroll
                for (int j = 0; j < 3; j++)
                    acc[i][j] = ffma2(ap[i], bp[j], acc[i][j]);
        }

        const float* bias = m ? kb : qb;
        float4 bz0 = *(const float4*)&bias[tw * 8];
        float4 bz1 = *(const float4*)&bias[tw * 8 + 4];
        float* outp = (m == 0) ? &g_Q[srcIdx][b][h * W_ + half * 96][0]
                               : &g_K[srcIdx ^ 1][b][h * W_ + half * 96][0];
        #pragma unroll
        for (int j = 0; j < 3; j++) {
            float2 t0 = unpack2(acc[0][j]), t1 = unpack2(acc[1][j]);
            float2 t2 = unpack2(acc[2][j]), t3 = unpack2(acc[3][j]);
            float* op = outp + (size_t)(lp + j) * 64 + tw * 8;
            *(float4*)op = make_float4(t0.x + bz0.x, t0.y + bz0.y,
                                       t1.x + bz0.z, t1.y + bz0.w);
            *(float4*)(op + 4) = make_float4(t2.x + bz1.x, t2.y + bz1.y,
                                             t3.x + bz1.z, t3.y + bz1.w);
        }
    }
}

// ---------------------------------------------------------------------------
// Cost volume via tf32 tensor-core GEMM S = Q * Kb^T + tiny gather epilogue.
// Block=(h,b,vol), 256 thr, dyn smem 69120B (3 CTAs/SM).
//   kb_s [192 x][68]  (c contiguous, stride 68: B-fragment LDS conflict-free)
//   S_s  [16 w][196]
//   q_s  [16 w][68]   (A-fragment LDS conflict-free)
// 12 m-tiles of 16 w; 8 warps each own 24 x-cols (3 n-tiles).
// ---------------------------------------------------------------------------
__global__ __launch_bounds__(256, 3) void cost_kernel(
    const float* __restrict__ d1, const float* __restrict__ d2,
    float* __restrict__ out)
{
    extern __shared__ float sm[];
    float* kb_s = sm;                 // 192*68 = 13056 floats
    float* S_s  = sm + 13056;         // 16*196 = 3136
    float* q_s  = sm + 13056 + 3136;  // 16*68  = 1088
    const int h = blockIdx.x, b = blockIdx.y, vol = blockIdx.z;
    const int tid = threadIdx.x;

    // y-blend K rows -> kb_s[x][c] (tf32-rounded), validity folded in.
    float ys  = h * (64.0f / 63.0f) - 0.5f;
    float y0f = floorf(ys);
    float ty  = ys - y0f;
    int iy0 = (int)y0f, iy1 = iy0 + 1;
    float wy0 = (iy0 >= 0 && iy0 < H_) ? (1.0f - ty) : 0.0f;
    float wy1 = (iy1 >= 0 && iy1 < H_) ? ty : 0.0f;
    int y0c = min(max(iy0, 0), H_ - 1);
    int y1c = min(max(iy1, 0), H_ - 1);
    const float4* k0 = (const float4*)&g_K[vol][b][y0c * W_][0];
    const float4* k1 = (const float4*)&g_K[vol][b][y1c * W_][0];
    #pragma unroll
    for (int e = tid; e < 3072; e += 256) {
        int xx = e >> 4, c4 = e & 15;
        float4 a = k0[e], c = k1[e];
        unsigned r0 = to_tf32(wy0 * a.x + wy1 * c.x);
        unsigned r1 = to_tf32(wy0 * a.y + wy1 * c.y);
        unsigned r2 = to_tf32(wy0 * a.z + wy1 * c.z);
        unsigned r3 = to_tf32(wy0 * a.w + wy1 * c.w);
        uint4* dst = (uint4*)&kb_s[xx * 68 + c4 * 4];
        *dst = make_uint4(r0, r1, r2, r3);
    }

    const int warp = tid >> 5, lane = tid & 31;
    const int g = lane >> 2, tig = lane & 3;   // mma group / thread-in-group
    const float* dispb = ((vol == 0) ? d1 : d2) + (size_t)b * D_ * HW_ + h * W_;
    float* outb = out + ((size_t)(vol * B_ + b) * D_) * HW_ + h * W_;

    #pragma unroll 1
    for (int mt = 0; mt < 12; ++mt) {
        const int w0 = mt * 16;
        // stage Q m-slice (tf32-rounded)
        {
            int m = tid >> 4, c4 = tid & 15;
            const float4 v = *(const float4*)&g_Q[vol][b][h * W_ + w0 + m][c4 * 4];
            uint4* dst = (uint4*)&q_s[m * 68 + c4 * 4];
            *dst = make_uint4(to_tf32(v.x), to_tf32(v.y), to_tf32(v.z), to_tf32(v.w));
        }
        __syncthreads();   // kb_s (first iter) + q_s ready; S_s free

        float c0[3], c1[3], c2[3], c3[3];
        #pragma unroll
        for (int n = 0; n < 3; n++) { c0[n]=0.f; c1[n]=0.f; c2[n]=0.f; c3[n]=0.f; }

        #pragma unroll
        for (int ks = 0; ks < 8; ++ks) {
            const int kc = ks * 8;
            unsigned a0 = __float_as_uint(q_s[g * 68 + kc + tig]);
            unsigned a1 = __float_as_uint(q_s[(g + 8) * 68 + kc + tig]);
            unsigned a2 = __float_as_uint(q_s[g * 68 + kc + tig + 4]);
            unsigned a3 = __float_as_uint(q_s[(g + 8) * 68 + kc + tig + 4]);
            #pragma unroll
            for (int n = 0; n < 3; ++n) {
                const int x0 = warp * 24 + n * 8;
                unsigned b0 = __float_as_uint(kb_s[(x0 + g) * 68 + kc + tig]);
                unsigned b1 = __float_as_uint(kb_s[(x0 + g) * 68 + kc + tig + 4]);
                asm volatile(
                    "mma.sync.aligned.m16n8k8.row.col.f32.tf32.tf32.f32 "
                    "{%0,%1,%2,%3}, {%4,%5,%6,%7}, {%8,%9}, {%0,%1,%2,%3};"
                    : "+f"(c0[n]), "+f"(c1[n]), "+f"(c2[n]), "+f"(c3[n])
                    : "r"(a0), "r"(a1), "r"(a2), "r"(a3), "r"(b0), "r"(b1));
            }
        }

        // write S strip
        #pragma unroll
        for (int n = 0; n < 3; ++n) {
            const int x0 = warp * 24 + n * 8;
            *(float2*)&S_s[g * 196 + x0 + tig * 2]       = make_float2(c0[n], c1[n]);
            *(float2*)&S_s[(g + 8) * 196 + x0 + tig * 2] = make_float2(c2[n], c3[n]);
        }
        __syncthreads();

        // gather epilogue: 24 d x 16 w outputs for this m-tile
        #pragma unroll
        for (int f = tid; f < 384; f += 256) {
            int d  = f >> 4;
            int wl = f & 15;
            float disp = __ldg(&dispb[d * HW_ + w0 + wl]);
            float xs  = disp * (192.0f / 191.0f) - 0.5f;
            float x0f = floorf(xs);
            float txf = xs - x0f;
            int ix0 = (int)x0f;
            float wx0 = (ix0 >= 0 && ix0 < W_) ? (1.0f - txf) : 0.0f;
            float wx1 = (ix0 + 1 >= 0 && ix0 + 1 < W_) ? txf : 0.0f;
            int x0c = min(max(ix0, 0), W_ - 1);
            int x1c = min(max(ix0 + 1, 0), W_ - 1);
            float sv = wx0 * S_s[wl * 196 + x0c] + wx1 * S_s[wl * 196 + x1c];
            outb[d * HW_ + w0 + wl] = sv * 0.015625f;
        }
        __syncthreads();   // S_s / q_s reusable next m-tile
    }
}

extern "C" void kernel_launch(void* const* d_in, const int* in_sizes, int n_in,
                              void* d_out, int out_size) {
    const float* x  = (const float*)d_in[0];
    const float* y  = (const float*)d_in[1];
    const float* d1 = (const float*)d_in[2];
    const float* d2 = (const float*)d_in[3];
    int wbase = (in_sizes[4] == 1) ? 5 : 4;
    const float* qw = (const float*)d_in[wbase + 0];
    const float* qb = (const float*)d_in[wbase + 1];
    const float* kw = (const float*)d_in[wbase + 2];
    const float* kb = (const float*)d_in[wbase + 3];
    float* out = (float*)d_out;

    cudaFuncSetAttribute(cost_kernel,
                         cudaFuncAttributeMaxDynamicSharedMemorySize, 69120);

    conv1x1_kernel<<<dim3(128, B_, 2), 256>>>(x, y, qw, qb, kw, kb);
    cost_kernel<<<dim3(H_, B_, 2), 256, 69120>>>(d1, d2, out);
}

// round 7
// speedup vs baseline: 1.6767x; 1.1677x over previous
#include <cuda_runtime.h>

#define B_ 4
#define C_ 64
#define H_ 64
#define W_ 192
#define D_ 24
#define HW_ (H_*W_)

// Feature maps [vol][b][h*w][c] (channel-contiguous per pixel).
__device__ float g_Q[2][B_][HW_][C_];
__device__ float g_K[2][B_][HW_][C_];

__device__ __forceinline__ unsigned to_tf32(float f) {
    unsigned u;
    asm("cvt.rna.tf32.f32 %0, %1;" : "=r"(u) : "f"(f));
    return u;
}
__device__ __forceinline__ void mma_tf32(float& c0, float& c1, float& c2, float& c3,
                                         unsigned a0, unsigned a1, unsigned a2, unsigned a3,
                                         unsigned b0, unsigned b1) {
    asm volatile(
        "mma.sync.aligned.m16n8k8.row.col.f32.tf32.tf32.f32 "
        "{%0,%1,%2,%3}, {%4,%5,%6,%7}, {%8,%9}, {%0,%1,%2,%3};"
        : "+f"(c0), "+f"(c1), "+f"(c2), "+f"(c3)
        : "r"(a0), "r"(a1), "r"(a2), "r"(a3), "r"(b0), "r"(b1));
}

// ---------------------------------------------------------------------------
// Conv1x1 via tf32 mma with 3-term precision split (fp32-accurate).
// Block=(h,b,src), 256 thr, 86 KB smem, 2 CTAs/SM.
//   in_s [64 cin][200] (channel-major; A-fragment banks (8t+g) conflict-free)
//   wt_s [2][64 cout][68] (raw W; col-major B operand, banks (4g+t) cf)
// m = 192 pix (12 tiles), n = 8 couts per warp, k = 64 (8 steps).
// ---------------------------------------------------------------------------
__global__ __launch_bounds__(256, 2) void conv1x1_kernel(
    const float* __restrict__ x, const float* __restrict__ y,
    const float* __restrict__ qw, const float* __restrict__ qb,
    const float* __restrict__ kw, const float* __restrict__ kb)
{
    extern __shared__ float csm[];
    float* in_s = csm;             // 64*200 = 12800
    float* wt_s = csm + 12800;     // 2*64*68 = 8704
    const int h = blockIdx.x, b = blockIdx.y, srcIdx = blockIdx.z;
    const float* src = (srcIdx == 0) ? x : y;
    const int tid = threadIdx.x;

    #pragma unroll
    for (int e4 = tid; e4 < 3072; e4 += 256) {
        int k = e4 / 48, w4 = e4 - k * 48;
        *(float4*)&in_s[k * 200 + w4 * 4] =
            *(const float4*)(src + ((size_t)(b * 64 + k)) * HW_ + h * 192 + w4 * 4);
    }
    #pragma unroll
    for (int e4 = tid; e4 < 2048; e4 += 256) {
        int m = e4 >> 10, idx = e4 & 1023;
        int o = idx >> 4, i4 = idx & 15;
        const float* w = m ? kw : qw;
        *(float4*)&wt_s[m * 4352 + o * 68 + i4 * 4] = *(const float4*)(w + o * 64 + i4 * 4);
    }
    __syncthreads();

    const int warp = tid >> 5, lane = tid & 31;
    const int g = lane >> 2, tig = lane & 3;
    const int n0 = warp * 8;

    #pragma unroll 1
    for (int m = 0; m < 2; ++m) {
        const float* Wm = wt_s + m * 4352;
        unsigned bh[8][2], bl[8][2];
        #pragma unroll
        for (int ks = 0; ks < 8; ks++) {
            float b0 = Wm[(n0 + g) * 68 + ks * 8 + tig];
            float b1 = Wm[(n0 + g) * 68 + ks * 8 + tig + 4];
            bh[ks][0] = to_tf32(b0);
            bl[ks][0] = to_tf32(b0 - __uint_as_float(bh[ks][0]));
            bh[ks][1] = to_tf32(b1);
            bl[ks][1] = to_tf32(b1 - __uint_as_float(bh[ks][1]));
        }
        const float* bias = m ? kb : qb;
        float2 bz = *(const float2*)&bias[n0 + 2 * tig];
        float* outp = (m == 0) ? &g_Q[srcIdx][b][h * W_][0]
                               : &g_K[srcIdx ^ 1][b][h * W_][0];

        #pragma unroll 1
        for (int mt = 0; mt < 12; ++mt) {
            const int m0 = mt * 16;
            float c0 = 0.f, c1 = 0.f, c2 = 0.f, c3 = 0.f;
            #pragma unroll
            for (int ks = 0; ks < 8; ks++) {
                float a0 = in_s[(ks * 8 + tig) * 200 + m0 + g];
                float a1 = in_s[(ks * 8 + tig) * 200 + m0 + g + 8];
                float a2 = in_s[(ks * 8 + tig + 4) * 200 + m0 + g];
                float a3 = in_s[(ks * 8 + tig + 4) * 200 + m0 + g + 8];
                unsigned ah0 = to_tf32(a0), ah1 = to_tf32(a1);
                unsigned ah2 = to_tf32(a2), ah3 = to_tf32(a3);
                unsigned al0 = to_tf32(a0 - __uint_as_float(ah0));
                unsigned al1 = to_tf32(a1 - __uint_as_float(ah1));
                unsigned al2 = to_tf32(a2 - __uint_as_float(ah2));
                unsigned al3 = to_tf32(a3 - __uint_as_float(ah3));
                mma_tf32(c0, c1, c2, c3, ah0, ah1, ah2, ah3, bh[ks][0], bh[ks][1]);
                mma_tf32(c0, c1, c2, c3, ah0, ah1, ah2, ah3, bl[ks][0], bl[ks][1]);
                mma_tf32(c0, c1, c2, c3, al0, al1, al2, al3, bh[ks][0], bh[ks][1]);
            }
            float* p0 = outp + (size_t)(m0 + g) * 64 + n0 + 2 * tig;
            *(float2*)p0 = make_float2(c0 + bz.x, c1 + bz.y);
            float* p1 = outp + (size_t)(m0 + g + 8) * 64 + n0 + 2 * tig;
            *(float2*)p1 = make_float2(c2 + bz.x, c3 + bz.y);
        }
    }
}

// ---------------------------------------------------------------------------
// Cost volume via tf32 mma + gather, software-pipelined (q/disp prefetched
// one tile ahead into registers). 256 thr, 69376 B smem, 3 CTAs/SM.
// ---------------------------------------------------------------------------
__global__ __launch_bounds__(256, 3) void cost_kernel(
    const float* __restrict__ d1, const float* __restrict__ d2,
    float* __restrict__ out)
{
    extern __shared__ float sm[];
    float* kb_s = sm;                  // 192*68 = 13056
    float* S_s  = sm + 13056;          // 16*200 = 3200
    float* q_s  = sm + 13056 + 3200;   // 16*68  = 1088
    const int h = blockIdx.x, b = blockIdx.y, vol = blockIdx.z;
    const int tid = threadIdx.x;

    // y-blend K rows -> kb_s[x][c] tf32, validity folded in.
    float ys  = h * (64.0f / 63.0f) - 0.5f;
    float y0f = floorf(ys);
    float ty  = ys - y0f;
    int iy0 = (int)y0f, iy1 = iy0 + 1;
    float wy0 = (iy0 >= 0 && iy0 < H_) ? (1.0f - ty) : 0.0f;
    float wy1 = (iy1 >= 0 && iy1 < H_) ? ty : 0.0f;
    int y0c = min(max(iy0, 0), H_ - 1);
    int y1c = min(max(iy1, 0), H_ - 1);
    const float4* k0 = (const float4*)&g_K[vol][b][y0c * W_][0];
    const float4* k1 = (const float4*)&g_K[vol][b][y1c * W_][0];
    #pragma unroll
    for (int e = tid; e < 3072; e += 256) {
        int xx = e >> 4, c4 = e & 15;
        float4 a = k0[e], c = k1[e];
        uint4* dst = (uint4*)&kb_s[xx * 68 + c4 * 4];
        *dst = make_uint4(to_tf32(wy0 * a.x + wy1 * c.x),
                          to_tf32(wy0 * a.y + wy1 * c.y),
                          to_tf32(wy0 * a.z + wy1 * c.z),
                          to_tf32(wy0 * a.w + wy1 * c.w));
    }

    const int warp = tid >> 5, lane = tid & 31;
    const int g = lane >> 2, tig = lane & 3;
    const int sm_ = tid >> 4, sc4 = tid & 15;       // q staging coords
    const int gd0 = tid >> 4, gw0 = tid & 15;       // gather coords f=tid
    const int gd1 = (tid + 256) >> 4, gw1 = tid & 15; // f=tid+256 (tid<128)
    const float* dispb = ((vol == 0) ? d1 : d2) + (size_t)b * D_ * HW_ + h * W_;
    const float* qbase = &g_Q[vol][b][h * W_][0];
    float* outb = out + ((size_t)(vol * B_ + b) * D_) * HW_ + h * W_;

    // prologue: q tile0 staged; q tile1 + disp tile0 in regs
    float4 qv = *(const float4*)(qbase + sm_ * 64 + sc4 * 4);
    *(uint4*)&q_s[sm_ * 68 + sc4 * 4] =
        make_uint4(to_tf32(qv.x), to_tf32(qv.y), to_tf32(qv.z), to_tf32(qv.w));
    qv = *(const float4*)(qbase + (16 + sm_) * 64 + sc4 * 4);
    float dsp0 = __ldg(&dispb[gd0 * HW_ + gw0]);
    float dsp1 = (tid < 128) ? __ldg(&dispb[gd1 * HW_ + gw1]) : 0.f;
    __syncthreads();

    #pragma unroll 1
    for (int mt = 0; mt < 12; ++mt) {
        const int w0 = mt * 16;

        float c0[3], c1[3], c2[3], c3[3];
        #pragma unroll
        for (int n = 0; n < 3; n++) { c0[n]=0.f; c1[n]=0.f; c2[n]=0.f; c3[n]=0.f; }
        #pragma unroll
        for (int ks = 0; ks < 8; ++ks) {
            const int kc = ks * 8;
            unsigned a0 = __float_as_uint(q_s[g * 68 + kc + tig]);
            unsigned a1 = __float_as_uint(q_s[(g + 8) * 68 + kc + tig]);
            unsigned a2 = __float_as_uint(q_s[g * 68 + kc + tig + 4]);
            unsigned a3 = __float_as_uint(q_s[(g + 8) * 68 + kc + tig + 4]);
            #pragma unroll
            for (int n = 0; n < 3; ++n) {
                const int x0 = warp * 24 + n * 8;
                unsigned b0 = __float_as_uint(kb_s[(x0 + g) * 68 + kc + tig]);
                unsigned b1 = __float_as_uint(kb_s[(x0 + g) * 68 + kc + tig + 4]);
                mma_tf32(c0[n], c1[n], c2[n], c3[n], a0, a1, a2, a3, b0, b1);
            }
        }
        __syncthreads();   // q_s(t) fully read; S_s gather(t-1) done

        #pragma unroll
        for (int n = 0; n < 3; ++n) {
            const int x0 = warp * 24 + n * 8;
            *(float2*)&S_s[g * 200 + x0 + tig * 2]       = make_float2(c0[n], c1[n]);
            *(float2*)&S_s[(g + 8) * 200 + x0 + tig * 2] = make_float2(c2[n], c3[n]);
        }
        if (mt < 11)
            *(uint4*)&q_s[sm_ * 68 + sc4 * 4] =
                make_uint4(to_tf32(qv.x), to_tf32(qv.y), to_tf32(qv.z), to_tf32(qv.w));
        if (mt < 10)
            qv = *(const float4*)(qbase + ((mt + 2) * 16 + sm_) * 64 + sc4 * 4);
        float nd0 = 0.f, nd1 = 0.f;
        if (mt < 11) {
            nd0 = __ldg(&dispb[gd0 * HW_ + w0 + 16 + gw0]);
            if (tid < 128) nd1 = __ldg(&dispb[gd1 * HW_ + w0 + 16 + gw1]);
        }
        __syncthreads();   // S_s + q_s(t+1) ready

        // gather tile t using prefetched disp
        {
            float xs  = dsp0 * (192.0f / 191.0f) - 0.5f;
            float x0f = floorf(xs);
            float txf = xs - x0f;
            int ix0 = (int)x0f;
            float wx0 = (ix0 >= 0 && ix0 < W_) ? (1.0f - txf) : 0.0f;
            float wx1 = (ix0 + 1 >= 0 && ix0 + 1 < W_) ? txf : 0.0f;
            int x0c = min(max(ix0, 0), W_ - 1);
            int x1c = min(max(ix0 + 1, 0), W_ - 1);
            float sv = wx0 * S_s[gw0 * 200 + x0c] + wx1 * S_s[gw0 * 200 + x1c];
            outb[gd0 * HW_ + w0 + gw0] = sv * 0.015625f;
        }
        if (tid < 128) {
            float xs  = dsp1 * (192.0f / 191.0f) - 0.5f;
            float x0f = floorf(xs);
            float txf = xs - x0f;
            int ix0 = (int)x0f;
            float wx0 = (ix0 >= 0 && ix0 < W_) ? (1.0f - txf) : 0.0f;
            float wx1 = (ix0 + 1 >= 0 && ix0 + 1 < W_) ? txf : 0.0f;
            int x0c = min(max(ix0, 0), W_ - 1);
            int x1c = min(max(ix0 + 1, 0), W_ - 1);
            float sv = wx0 * S_s[gw1 * 200 + x0c] + wx1 * S_s[gw1 * 200 + x1c];
            outb[gd1 * HW_ + w0 + gw1] = sv * 0.015625f;
        }
        dsp0 = nd0; dsp1 = nd1;
    }
}

extern "C" void kernel_launch(void* const* d_in, const int* in_sizes, int n_in,
                              void* d_out, int out_size) {
    const float* x  = (const float*)d_in[0];
    const float* y  = (const float*)d_in[1];
    const float* d1 = (const float*)d_in[2];
    const float* d2 = (const float*)d_in[3];
    int wbase = (in_sizes[4] == 1) ? 5 : 4;
    const float* qw = (const float*)d_in[wbase + 0];
    const float* qb = (const float*)d_in[wbase + 1];
    const float* kw = (const float*)d_in[wbase + 2];
    const float* kb = (const float*)d_in[wbase + 3];
    float* out = (float*)d_out;

    cudaFuncSetAttribute(conv1x1_kernel,
                         cudaFuncAttributeMaxDynamicSharedMemorySize, 86016);
    cudaFuncSetAttribute(cost_kernel,
                         cudaFuncAttributeMaxDynamicSharedMemorySize, 69376);

    conv1x1_kernel<<<dim3(H_, B_, 2), 256, 86016>>>(x, y, qw, qb, kw, kb);
    cost_kernel<<<dim3(H_, B_, 2), 256, 69376>>>(d1, d2, out);
}

// round 8
// speedup vs baseline: 1.8670x; 1.1135x over previous
#include <cuda_runtime.h>

#define B_ 4
#define C_ 64
#define H_ 64
#define W_ 192
#define D_ 24
#define HW_ (H_*W_)

// Z = src·M per source; dot maps du = src·u, dv = src·v.
__device__ float g_Z[2][B_][HW_][C_];
__device__ float g_du[2][B_][HW_];
__device__ float g_dv[2][B_][HW_];
__device__ float g_Mt[C_][C_];   // g_Mt[j][i] = sum_c kw[c][j]*qw[c][i]
__device__ float g_uv[2][C_];    // [0]=u, [1]=v
__device__ float g_s0;

__device__ __forceinline__ unsigned to_tf32(float f) {
    unsigned u;
    asm("cvt.rna.tf32.f32 %0, %1;" : "=r"(u) : "f"(f));
    return u;
}
__device__ __forceinline__ void mma_tf32(float& c0, float& c1, float& c2, float& c3,
                                         unsigned a0, unsigned a1, unsigned a2, unsigned a3,
                                         unsigned b0, unsigned b1) {
    asm volatile(
        "mma.sync.aligned.m16n8k8.row.col.f32.tf32.tf32.f32 "
        "{%0,%1,%2,%3}, {%4,%5,%6,%7}, {%8,%9}, {%0,%1,%2,%3};"
        : "+f"(c0), "+f"(c1), "+f"(c2), "+f"(c3)
        : "r"(a0), "r"(a1), "r"(a2), "r"(a3), "r"(b0), "r"(b1));
}

// ---------------------------------------------------------------------------
// Prep: M = qw^T kw (stored [j][i]), u = qw^T kb, v = kw^T qb, s0 = qb.kb.
// ---------------------------------------------------------------------------
__global__ void prep_kernel(const float* __restrict__ qw, const float* __restrict__ qb,
                            const float* __restrict__ kw, const float* __restrict__ kb)
{
    __shared__ float qs[64][64], ks_[64][64];
    const int tid = threadIdx.x;
    for (int e4 = tid; e4 < 1024; e4 += 256) {
        int c = e4 >> 4, i4 = e4 & 15;
        *(float4*)&qs[c][i4 * 4]  = *(const float4*)(qw + c * 64 + i4 * 4);
        *(float4*)&ks_[c][i4 * 4] = *(const float4*)(kw + c * 64 + i4 * 4);
    }
    __syncthreads();
    const int j = tid >> 2, i0 = (tid & 3) * 16;
    float acc[16];
    #pragma unroll
    for (int t = 0; t < 16; t++) acc[t] = 0.f;
    for (int c = 0; c < 64; ++c) {
        float kv = ks_[c][j];
        #pragma unroll
        for (int t = 0; t < 16; t++) acc[t] += kv * qs[c][i0 + t];
    }
    #pragma unroll
    for (int t = 0; t < 16; t++) g_Mt[j][i0 + t] = acc[t];
    if (tid < 64) {
        float uu = 0.f, vv = 0.f;
        for (int c = 0; c < 64; ++c) {
            uu += qs[c][tid] * __ldg(&kb[c]);
            vv += ks_[c][tid] * __ldg(&qb[c]);
        }
        g_uv[0][tid] = uu;
        g_uv[1][tid] = vv;
    }
    if (tid == 0) {
        float s = 0.f;
        for (int c = 0; c < 64; ++c) s += __ldg(&qb[c]) * __ldg(&kb[c]);
        g_s0 = s;
    }
}

// ---------------------------------------------------------------------------
// Z kernel: Z = src·M (fp32-accurate via 3-term tf32 split) + dot maps.
// Block=(h,b,src), 256 thr, 69120 B smem, 3 CTAs/SM.
// ---------------------------------------------------------------------------
__global__ __launch_bounds__(256, 3) void z_kernel(
    const float* __restrict__ x, const float* __restrict__ y)
{
    extern __shared__ float zsm[];
    float* in_s = zsm;              // 64*200
    float* M_s  = zsm + 12800;      // 64*68
    float* uv_s = zsm + 12800 + 4352;  // 128
    const int h = blockIdx.x, b = blockIdx.y, srcIdx = blockIdx.z;
    const float* src = srcIdx ? y : x;
    const int tid = threadIdx.x;

    #pragma unroll
    for (int e4 = tid; e4 < 3072; e4 += 256) {
        int k = e4 / 48, w4 = e4 - k * 48;
        *(float4*)&in_s[k * 200 + w4 * 4] =
            *(const float4*)(src + ((size_t)(b * 64 + k)) * HW_ + h * 192 + w4 * 4);
    }
    #pragma unroll
    for (int e4 = tid; e4 < 1024; e4 += 256) {
        int j = e4 >> 4, i4 = e4 & 15;
        *(float4*)&M_s[j * 68 + i4 * 4] = *(const float4*)&g_Mt[j][i4 * 4];
    }
    if (tid < 128) uv_s[tid] = g_uv[tid >> 6][tid & 63];
    __syncthreads();

    const int warp = tid >> 5, lane = tid & 31;
    const int g = lane >> 2, tig = lane & 3;
    const int n0 = warp * 8;

    unsigned bh[8][2], bl[8][2];
    #pragma unroll
    for (int ks = 0; ks < 8; ks++) {
        float b0 = M_s[(n0 + g) * 68 + ks * 8 + tig];
        float b1 = M_s[(n0 + g) * 68 + ks * 8 + tig + 4];
        bh[ks][0] = to_tf32(b0);
        bl[ks][0] = to_tf32(b0 - __uint_as_float(bh[ks][0]));
        bh[ks][1] = to_tf32(b1);
        bl[ks][1] = to_tf32(b1 - __uint_as_float(bh[ks][1]));
    }

    float* outp = &g_Z[srcIdx][b][h * W_][0];
    #pragma unroll 1
    for (int mt = 0; mt < 12; ++mt) {
        const int m0 = mt * 16;
        float c0 = 0.f, c1 = 0.f, c2 = 0.f, c3 = 0.f;
        #pragma unroll
        for (int ks = 0; ks < 8; ks++) {
            float a0 = in_s[(ks * 8 + tig) * 200 + m0 + g];
            float a1 = in_s[(ks * 8 + tig) * 200 + m0 + g + 8];
            float a2 = in_s[(ks * 8 + tig + 4) * 200 + m0 + g];
            float a3 = in_s[(ks * 8 + tig + 4) * 200 + m0 + g + 8];
            unsigned ah0 = to_tf32(a0), ah1 = to_tf32(a1);
            unsigned ah2 = to_tf32(a2), ah3 = to_tf32(a3);
            unsigned al0 = to_tf32(a0 - __uint_as_float(ah0));
            unsigned al1 = to_tf32(a1 - __uint_as_float(ah1));
            unsigned al2 = to_tf32(a2 - __uint_as_float(ah2));
            unsigned al3 = to_tf32(a3 - __uint_as_float(ah3));
            mma_tf32(c0, c1, c2, c3, ah0, ah1, ah2, ah3, bh[ks][0], bh[ks][1]);
            mma_tf32(c0, c1, c2, c3, ah0, ah1, ah2, ah3, bl[ks][0], bl[ks][1]);
            mma_tf32(c0, c1, c2, c3, al0, al1, al2, al3, bh[ks][0], bh[ks][1]);
        }
        *(float2*)(outp + (size_t)(m0 + g) * 64 + n0 + 2 * tig)     = make_float2(c0, c1);
        *(float2*)(outp + (size_t)(m0 + g + 8) * 64 + n0 + 2 * tig) = make_float2(c2, c3);
    }

    // dot maps (fp32 exact)
    if (tid < 192) {
        float du = 0.f, dv = 0.f;
        for (int c = 0; c < 64; ++c) {
            float xv = in_s[c * 200 + tid];
            du += xv * uv_s[c];
            dv += xv * uv_s[64 + c];
        }
        g_du[srcIdx][b][h * W_ + tid] = du;
        g_dv[srcIdx][b][h * W_ + tid] = dv;
    }
}

// ---------------------------------------------------------------------------
// Cost volume: S = Z·Yb^T (tf32 mma) + rank-1 terms + gather epilogue.
// kb_s now [c][x] stride 200 (staging AND fragment reads conflict-free).
// Block=(h,b,vol), 256 thr, 69120 B smem, 3 CTAs/SM, R7 pipelining kept.
// ---------------------------------------------------------------------------
__global__ __launch_bounds__(256, 3) void cost_kernel(
    const float* __restrict__ x, const float* __restrict__ y,
    const float* __restrict__ d1, const float* __restrict__ d2,
    float* __restrict__ out)
{
    extern __shared__ float sm[];
    float* kb_s   = sm;            // 64*200 = 12800
    float* S_s    = sm + 12800;    // 16*200 = 3200
    float* q_s    = sm + 16000;    // 16*68  = 1088
    float* dvyb_s = sm + 17088;    // 192
    const int h = blockIdx.x, b = blockIdx.y, vol = blockIdx.z;
    const int tid = threadIdx.x;

    float ys  = h * (64.0f / 63.0f) - 0.5f;
    float y0f = floorf(ys);
    float ty  = ys - y0f;
    int iy0 = (int)y0f, iy1 = iy0 + 1;
    float wy0 = (iy0 >= 0 && iy0 < H_) ? (1.0f - ty) : 0.0f;
    float wy1 = (iy1 >= 0 && iy1 < H_) ? ty : 0.0f;
    int y0c = min(max(iy0, 0), H_ - 1);
    int y1c = min(max(iy1, 0), H_ - 1);
    const float wsum = wy0 + wy1;

    const float* srcB = (vol == 0) ? y : x;   // B-side raw source
    const int s2 = vol ^ 1;                   // its index in g_dv

    // blend raw rows -> kb_s[c][x] tf32 (coalesced, conflict-free)
    #pragma unroll
    for (int e4 = tid; e4 < 3072; e4 += 256) {
        int c = e4 / 48, w4 = e4 - c * 48;
        const float* r0 = srcB + ((size_t)(b * 64 + c) * H_ + y0c) * W_ + w4 * 4;
        const float* r1 = srcB + ((size_t)(b * 64 + c) * H_ + y1c) * W_ + w4 * 4;
        float4 a = *(const float4*)r0, cc = *(const float4*)r1;
        *(uint4*)&kb_s[c * 200 + w4 * 4] =
            make_uint4(to_tf32(wy0 * a.x + wy1 * cc.x),
                       to_tf32(wy0 * a.y + wy1 * cc.y),
                       to_tf32(wy0 * a.z + wy1 * cc.z),
                       to_tf32(wy0 * a.w + wy1 * cc.w));
    }
    if (tid < 192)
        dvyb_s[tid] = wy0 * g_dv[s2][b][y0c * W_ + tid]
                    + wy1 * g_dv[s2][b][y1c * W_ + tid];
    const float rho0 = wsum * g_s0;

    const int warp = tid >> 5, lane = tid & 31;
    const int g = lane >> 2, tig = lane & 3;
    const int sm_ = tid >> 4, sc4 = tid & 15;
    const int gd0 = tid >> 4, gw0 = tid & 15;
    const int gd1 = (tid + 256) >> 4, gw1 = tid & 15;
    const float* dispb = ((vol == 0) ? d1 : d2) + (size_t)b * D_ * HW_ + h * W_;
    const float* qbase = &g_Z[vol][b][h * W_][0];
    const float* dubase = &g_du[vol][b][h * W_];
    float* outb = out + ((size_t)(vol * B_ + b) * D_) * HW_ + h * W_;

    float4 qv = *(const float4*)(qbase + sm_ * 64 + sc4 * 4);
    *(uint4*)&q_s[sm_ * 68 + sc4 * 4] =
        make_uint4(to_tf32(qv.x), to_tf32(qv.y), to_tf32(qv.z), to_tf32(qv.w));
    qv = *(const float4*)(qbase + (16 + sm_) * 64 + sc4 * 4);
    float dsp0 = __ldg(&dispb[gd0 * HW_ + gw0]);
    float dsp1 = (tid < 128) ? __ldg(&dispb[gd1 * HW_ + gw1]) : 0.f;
    __syncthreads();

    #pragma unroll 1
    for (int mt = 0; mt < 12; ++mt) {
        const int w0 = mt * 16;
        // rank-1 row terms (L1 LDG issued early; consumed after syncA)
        float rw0 = wsum * __ldg(&dubase[w0 + g]) + rho0;
        float rw1 = wsum * __ldg(&dubase[w0 + g + 8]) + rho0;

        float c0[3], c1[3], c2[3], c3[3];
        #pragma unroll
        for (int n = 0; n < 3; n++) { c0[n]=0.f; c1[n]=0.f; c2[n]=0.f; c3[n]=0.f; }
        #pragma unroll
        for (int ks = 0; ks < 8; ++ks) {
            const int kc = ks * 8;
            unsigned a0 = __float_as_uint(q_s[g * 68 + kc + tig]);
            unsigned a1 = __float_as_uint(q_s[(g + 8) * 68 + kc + tig]);
            unsigned a2 = __float_as_uint(q_s[g * 68 + kc + tig + 4]);
            unsigned a3 = __float_as_uint(q_s[(g + 8) * 68 + kc + tig + 4]);
            #pragma unroll
            for (int n = 0; n < 3; ++n) {
                const int x0 = warp * 24 + n * 8;
                unsigned b0 = __float_as_uint(kb_s[(kc + tig) * 200 + x0 + g]);
                unsigned b1 = __float_as_uint(kb_s[(kc + tig + 4) * 200 + x0 + g]);
                mma_tf32(c0[n], c1[n], c2[n], c3[n], a0, a1, a2, a3, b0, b1);
            }
        }
        __syncthreads();   // q_s(t) read done; S_s gather(t-1) done

        #pragma unroll
        for (int n = 0; n < 3; ++n) {
            const int x0 = warp * 24 + n * 8;
            const int col = x0 + tig * 2;
            *(float2*)&S_s[g * 200 + col] =
                make_float2(c0[n] + rw0 + dvyb_s[col], c1[n] + rw0 + dvyb_s[col + 1]);
            *(float2*)&S_s[(g + 8) * 200 + col] =
                make_float2(c2[n] + rw1 + dvyb_s[col], c3[n] + rw1 + dvyb_s[col + 1]);
        }
        if (mt < 11)
            *(uint4*)&q_s[sm_ * 68 + sc4 * 4] =
                make_uint4(to_tf32(qv.x), to_tf32(qv.y), to_tf32(qv.z), to_tf32(qv.w));
        if (mt < 10)
            qv = *(const float4*)(qbase + ((mt + 2) * 16 + sm_) * 64 + sc4 * 4);
        float nd0 = 0.f, nd1 = 0.f;
        if (mt < 11) {
            nd0 = __ldg(&dispb[gd0 * HW_ + w0 + 16 + gw0]);
            if (tid < 128) nd1 = __ldg(&dispb[gd1 * HW_ + w0 + 16 + gw1]);
        }
        __syncthreads();   // S_s + q_s(t+1) ready

        {
            float xs  = dsp0 * (192.0f / 191.0f) - 0.5f;
            float x0f = floorf(xs);
            float txf = xs - x0f;
            int ix0 = (int)x0f;
            float wx0 = (ix0 >= 0 && ix0 < W_) ? (1.0f - txf) : 0.0f;
            float wx1 = (ix0 + 1 >= 0 && ix0 + 1 < W_) ? txf : 0.0f;
            int x0c = min(max(ix0, 0), W_ - 1);
            int x1c = min(max(ix0 + 1, 0), W_ - 1);
            float sv = wx0 * S_s[gw0 * 200 + x0c] + wx1 * S_s[gw0 * 200 + x1c];
            outb[gd0 * HW_ + w0 + gw0] = sv * 0.015625f;
        }
        if (tid < 128) {
            float xs  = dsp1 * (192.0f / 191.0f) - 0.5f;
            float x0f = floorf(xs);
            float txf = xs - x0f;
            int ix0 = (int)x0f;
            float wx0 = (ix0 >= 0 && ix0 < W_) ? (1.0f - txf) : 0.0f;
            float wx1 = (ix0 + 1 >= 0 && ix0 + 1 < W_) ? txf : 0.0f;
            int x0c = min(max(ix0, 0), W_ - 1);
            int x1c = min(max(ix0 + 1, 0), W_ - 1);
            float sv = wx0 * S_s[gw1 * 200 + x0c] + wx1 * S_s[gw1 * 200 + x1c];
            outb[gd1 * HW_ + w0 + gw1] = sv * 0.015625f;
        }
        dsp0 = nd0; dsp1 = nd1;
    }
}

extern "C" void kernel_launch(void* const* d_in, const int* in_sizes, int n_in,
                              void* d_out, int out_size) {
    const float* x  = (const float*)d_in[0];
    const float* y  = (const float*)d_in[1];
    const float* d1 = (const float*)d_in[2];
    const float* d2 = (const float*)d_in[3];
    int wbase = (in_sizes[4] == 1) ? 5 : 4;
    const float* qw = (const float*)d_in[wbase + 0];
    const float* qb = (const float*)d_in[wbase + 1];
    const float* kw = (const float*)d_in[wbase + 2];
    const float* kb = (const float*)d_in[wbase + 3];
    float* out = (float*)d_out;

    cudaFuncSetAttribute(z_kernel,
                         cudaFuncAttributeMaxDynamicSharedMemorySize, 69120);
    cudaFuncSetAttribute(cost_kernel,
                         cudaFuncAttributeMaxDynamicSharedMemorySize, 69120);

    prep_kernel<<<1, 256>>>(qw, qb, kw, kb);
    z_kernel<<<dim3(H_, B_, 2), 256, 69120>>>(x, y);
    cost_kernel<<<dim3(H_, B_, 2), 256, 69120>>>(x, y, d1, d2, out);
}

// round 9
// speedup vs baseline: 2.0919x; 1.1205x over previous
#include <cuda_runtime.h>

#define B_ 4
#define C_ 64
#define H_ 64
#define W_ 192
#define D_ 24
#define HW_ (H_*W_)

// Z = src·M (stored tf32-rounded); dot maps du = src·u, dv = src·v.
__device__ float g_Z[2][B_][HW_][C_];
__device__ float g_du[2][B_][HW_];
__device__ float g_dv[2][B_][HW_];
__device__ float g_Mt[C_][C_];   // g_Mt[j][i] = sum_c kw[c][j]*qw[c][i]
__device__ float g_uv[2][C_];    // [0]=u, [1]=v
__device__ float g_s0;

__device__ __forceinline__ unsigned to_tf32(float f) {
    unsigned u;
    asm("cvt.rna.tf32.f32 %0, %1;" : "=r"(u) : "f"(f));
    return u;
}
__device__ __forceinline__ void mma_tf32(float& c0, float& c1, float& c2, float& c3,
                                         unsigned a0, unsigned a1, unsigned a2, unsigned a3,
                                         unsigned b0, unsigned b1) {
    asm volatile(
        "mma.sync.aligned.m16n8k8.row.col.f32.tf32.tf32.f32 "
        "{%0,%1,%2,%3}, {%4,%5,%6,%7}, {%8,%9}, {%0,%1,%2,%3};"
        : "+f"(c0), "+f"(c1), "+f"(c2), "+f"(c3)
        : "r"(a0), "r"(a1), "r"(a2), "r"(a3), "r"(b0), "r"(b1));
}

// ---------------------------------------------------------------------------
// Prep, parallel: blocks 0..15 compute 4 rows of M each; block 16 does u/v/s0.
// ---------------------------------------------------------------------------
__global__ void prep_kernel(const float* __restrict__ qw, const float* __restrict__ qb,
                            const float* __restrict__ kw, const float* __restrict__ kb)
{
    const int tid = threadIdx.x, bid = blockIdx.x;
    if (bid < 16) {
        const int j = bid * 4 + (tid >> 6);
        const int i = tid & 63;
        float acc = 0.f;
        #pragma unroll 8
        for (int c = 0; c < 64; ++c)
            acc += __ldg(&kw[c * 64 + j]) * __ldg(&qw[c * 64 + i]);
        g_Mt[j][i] = acc;
    } else {
        if (tid < 128) {
            const int m = tid >> 6, i = tid & 63;   // m=0 -> u, m=1 -> v
            const float* wm = m ? kw : qw;
            const float* bm = m ? qb : kb;
            float acc = 0.f;
            #pragma unroll 8
            for (int c = 0; c < 64; ++c)
                acc += __ldg(&wm[c * 64 + i]) * __ldg(&bm[c]);
            g_uv[m][i] = acc;
        } else if (tid < 160) {
            const int lane = tid & 31;
            float p0 = __ldg(&qb[lane])      * __ldg(&kb[lane]);
            float p1 = __ldg(&qb[lane + 32]) * __ldg(&kb[lane + 32]);
            float s = p0 + p1;
            s += __shfl_xor_sync(0xffffffffu, s, 1);
            s += __shfl_xor_sync(0xffffffffu, s, 2);
            s += __shfl_xor_sync(0xffffffffu, s, 4);
            s += __shfl_xor_sync(0xffffffffu, s, 8);
            s += __shfl_xor_sync(0xffffffffu, s, 16);
            if (lane == 0) g_s0 = s;
        }
    }
}

// ---------------------------------------------------------------------------
// Z kernel: Z = src·M (fp32-accurate 3-term tf32 split), stored tf32-rounded,
// + dot maps. smem = in_s only (51200 B) -> 4 CTAs/SM, single wave.
// M / uv read via L1-hot __ldg.
// ---------------------------------------------------------------------------
__global__ __launch_bounds__(256, 4) void z_kernel(
    const float* __restrict__ x, const float* __restrict__ y)
{
    extern __shared__ float zsm[];
    float* in_s = zsm;              // 64*200 = 12800 floats
    const int h = blockIdx.x, b = blockIdx.y, srcIdx = blockIdx.z;
    const float* src = srcIdx ? y : x;
    const int tid = threadIdx.x;

    #pragma unroll
    for (int e4 = tid; e4 < 3072; e4 += 256) {
        int k = e4 / 48, w4 = e4 - k * 48;
        *(float4*)&in_s[k * 200 + w4 * 4] =
            *(const float4*)(src + ((size_t)(b * 64 + k)) * HW_ + h * 192 + w4 * 4);
    }
    __syncthreads();

    const int warp = tid >> 5, lane = tid & 31;
    const int g = lane >> 2, tig = lane & 3;
    const int n0 = warp * 8;

    unsigned bh[8][2], bl[8][2];
    #pragma unroll
    for (int ks = 0; ks < 8; ks++) {
        float b0 = __ldg(&g_Mt[n0 + g][ks * 8 + tig]);
        float b1 = __ldg(&g_Mt[n0 + g][ks * 8 + tig + 4]);
        bh[ks][0] = to_tf32(b0);
        bl[ks][0] = to_tf32(b0 - __uint_as_float(bh[ks][0]));
        bh[ks][1] = to_tf32(b1);
        bl[ks][1] = to_tf32(b1 - __uint_as_float(bh[ks][1]));
    }

    float* outp = &g_Z[srcIdx][b][h * W_][0];
    #pragma unroll 1
    for (int mt = 0; mt < 12; ++mt) {
        const int m0 = mt * 16;
        float c0 = 0.f, c1 = 0.f, c2 = 0.f, c3 = 0.f;
        #pragma unroll
        for (int ks = 0; ks < 8; ks++) {
            float a0 = in_s[(ks * 8 + tig) * 200 + m0 + g];
            float a1 = in_s[(ks * 8 + tig) * 200 + m0 + g + 8];
            float a2 = in_s[(ks * 8 + tig + 4) * 200 + m0 + g];
            float a3 = in_s[(ks * 8 + tig + 4) * 200 + m0 + g + 8];
            unsigned ah0 = to_tf32(a0), ah1 = to_tf32(a1);
            unsigned ah2 = to_tf32(a2), ah3 = to_tf32(a3);
            unsigned al0 = to_tf32(a0 - __uint_as_float(ah0));
            unsigned al1 = to_tf32(a1 - __uint_as_float(ah1));
            unsigned al2 = to_tf32(a2 - __uint_as_float(ah2));
            unsigned al3 = to_tf32(a3 - __uint_as_float(ah3));
            mma_tf32(c0, c1, c2, c3, ah0, ah1, ah2, ah3, bh[ks][0], bh[ks][1]);
            mma_tf32(c0, c1, c2, c3, ah0, ah1, ah2, ah3, bl[ks][0], bl[ks][1]);
            mma_tf32(c0, c1, c2, c3, al0, al1, al2, al3, bh[ks][0], bh[ks][1]);
        }
        // store tf32-rounded (cost stages without cvt)
        *(uint2*)(outp + (size_t)(m0 + g) * 64 + n0 + 2 * tig) =
            make_uint2(to_tf32(c0), to_tf32(c1));
        *(uint2*)(outp + (size_t)(m0 + g + 8) * 64 + n0 + 2 * tig) =
            make_uint2(to_tf32(c2), to_tf32(c3));
    }

    // dot maps (fp32 exact); u/v via uniform L1 loads
    if (tid < 192) {
        float du = 0.f, dv = 0.f;
        #pragma unroll 8
        for (int c = 0; c < 64; ++c) {
            float xv = in_s[c * 200 + tid];
            du += xv * __ldg(&g_uv[0][c]);
            dv += xv * __ldg(&g_uv[1][c]);
        }
        g_du[srcIdx][b][h * W_ + tid] = du;
        g_dv[srcIdx][b][h * W_ + tid] = dv;
    }
}

// ---------------------------------------------------------------------------
// Cost volume: S = Z·Yb^T (pure tf32 mma); rank-1 + dv + const terms folded
// into the gather epilogue. Block=(h,b,vol), 256 thr, 69120 B, 3 CTAs/SM.
// ---------------------------------------------------------------------------
__global__ __launch_bounds__(256, 3) void cost_kernel(
    const float* __restrict__ x, const float* __restrict__ y,
    const float* __restrict__ d1, const float* __restrict__ d2,
    float* __restrict__ out)
{
    extern __shared__ float sm[];
    float* kb_s   = sm;            // 64*200 = 12800
    float* S_s    = sm + 12800;    // 16*200 = 3200
    float* q_s    = sm + 16000;    // 16*68  = 1088
    float* dvyb_s = sm + 17088;    // 192
    const int h = blockIdx.x, b = blockIdx.y, vol = blockIdx.z;
    const int tid = threadIdx.x;

    float ys  = h * (64.0f / 63.0f) - 0.5f;
    float y0f = floorf(ys);
    float ty  = ys - y0f;
    int iy0 = (int)y0f, iy1 = iy0 + 1;
    float wy0 = (iy0 >= 0 && iy0 < H_) ? (1.0f - ty) : 0.0f;
    float wy1 = (iy1 >= 0 && iy1 < H_) ? ty : 0.0f;
    int y0c = min(max(iy0, 0), H_ - 1);
    int y1c = min(max(iy1, 0), H_ - 1);
    const float wsum = wy0 + wy1;

    const float* srcB = (vol == 0) ? y : x;
    const int s2 = vol ^ 1;

    #pragma unroll
    for (int e4 = tid; e4 < 3072; e4 += 256) {
        int c = e4 / 48, w4 = e4 - c * 48;
        const float* r0 = srcB + ((size_t)(b * 64 + c) * H_ + y0c) * W_ + w4 * 4;
        const float* r1 = srcB + ((size_t)(b * 64 + c) * H_ + y1c) * W_ + w4 * 4;
        float4 a = *(const float4*)r0, cc = *(const float4*)r1;
        *(uint4*)&kb_s[c * 200 + w4 * 4] =
            make_uint4(to_tf32(wy0 * a.x + wy1 * cc.x),
                       to_tf32(wy0 * a.y + wy1 * cc.y),
                       to_tf32(wy0 * a.z + wy1 * cc.z),
                       to_tf32(wy0 * a.w + wy1 * cc.w));
    }
    if (tid < 192)
        dvyb_s[tid] = wy0 * g_dv[s2][b][y0c * W_ + tid]
                    + wy1 * g_dv[s2][b][y1c * W_ + tid];
    const float rho0 = wsum * g_s0;

    const int warp = tid >> 5, lane = tid & 31;
    const int g = lane >> 2, tig = lane & 3;
    const int sm_ = tid >> 4, sc4 = tid & 15;
    const int gd0 = tid >> 4, gw0 = tid & 15;
    const int gd1 = (tid + 256) >> 4, gw1 = tid & 15;
    const float* dispb = ((vol == 0) ? d1 : d2) + (size_t)b * D_ * HW_ + h * W_;
    const float* qbase = &g_Z[vol][b][h * W_][0];
    const float* dubase = &g_du[vol][b][h * W_];
    float* outb = out + ((size_t)(vol * B_ + b) * D_) * HW_ + h * W_;

    // prologue: q tile0 staged (plain copy, Z pre-rounded); q tile1 + disp in regs
    float4 qv = *(const float4*)(qbase + sm_ * 64 + sc4 * 4);
    *(float4*)&q_s[sm_ * 68 + sc4 * 4] = qv;
    qv = *(const float4*)(qbase + (16 + sm_) * 64 + sc4 * 4);
    float dsp0 = __ldg(&dispb[gd0 * HW_ + gw0]);
    float dsp1 = (tid < 128) ? __ldg(&dispb[gd1 * HW_ + gw1]) : 0.f;
    __syncthreads();

    #pragma unroll 1
    for (int mt = 0; mt < 12; ++mt) {
        const int w0 = mt * 16;

        float c0[3], c1[3], c2[3], c3[3];
        #pragma unroll
        for (int n = 0; n < 3; n++) { c0[n]=0.f; c1[n]=0.f; c2[n]=0.f; c3[n]=0.f; }
        #pragma unroll
        for (int ks = 0; ks < 8; ++ks) {
            const int kc = ks * 8;
            unsigned a0 = __float_as_uint(q_s[g * 68 + kc + tig]);
            unsigned a1 = __float_as_uint(q_s[(g + 8) * 68 + kc + tig]);
            unsigned a2 = __float_as_uint(q_s[g * 68 + kc + tig + 4]);
            unsigned a3 = __float_as_uint(q_s[(g + 8) * 68 + kc + tig + 4]);
            #pragma unroll
            for (int n = 0; n < 3; ++n) {
                const int x0 = warp * 24 + n * 8;
                unsigned b0 = __float_as_uint(kb_s[(kc + tig) * 200 + x0 + g]);
                unsigned b1 = __float_as_uint(kb_s[(kc + tig + 4) * 200 + x0 + g]);
                mma_tf32(c0[n], c1[n], c2[n], c3[n], a0, a1, a2, a3, b0, b1);
            }
        }
        __syncthreads();   // q_s(t) read done; gather(t-1) done

        #pragma unroll
        for (int n = 0; n < 3; ++n) {
            const int x0 = warp * 24 + n * 8;
            const int col = x0 + tig * 2;
            *(float2*)&S_s[g * 200 + col]       = make_float2(c0[n], c1[n]);
            *(float2*)&S_s[(g + 8) * 200 + col] = make_float2(c2[n], c3[n]);
        }
        if (mt < 11)
            *(float4*)&q_s[sm_ * 68 + sc4 * 4] = qv;
        if (mt < 10)
            qv = *(const float4*)(qbase + ((mt + 2) * 16 + sm_) * 64 + sc4 * 4);
        float nd0 = 0.f, nd1 = 0.f;
        if (mt < 11) {
            nd0 = __ldg(&dispb[gd0 * HW_ + w0 + 16 + gw0]);
            if (tid < 128) nd1 = __ldg(&dispb[gd1 * HW_ + w0 + 16 + gw1]);
        }
        __syncthreads();   // S_s + q_s(t+1) ready

        {
            float xs  = dsp0 * (192.0f / 191.0f) - 0.5f;
            float x0f = floorf(xs);
            float txf = xs - x0f;
            int ix0 = (int)x0f;
            float wx0 = (ix0 >= 0 && ix0 < W_) ? (1.0f - txf) : 0.0f;
            float wx1 = (ix0 + 1 >= 0 && ix0 + 1 < W_) ? txf : 0.0f;
            int x0c = min(max(ix0, 0), W_ - 1);
            int x1c = min(max(ix0 + 1, 0), W_ - 1);
            float rw = wsum * __ldg(&dubase[w0 + gw0]) + rho0;
            float sv = wx0 * (S_s[gw0 * 200 + x0c] + dvyb_s[x0c])
                     + wx1 * (S_s[gw0 * 200 + x1c] + dvyb_s[x1c])
                     + (wx0 + wx1) * rw;
            outb[gd0 * HW_ + w0 + gw0] = sv * 0.015625f;
        }
        if (tid < 128) {
            float xs  = dsp1 * (192.0f / 191.0f) - 0.5f;
            float x0f = floorf(xs);
            float txf = xs - x0f;
            int ix0 = (int)x0f;
            float wx0 = (ix0 >= 0 && ix0 < W_) ? (1.0f - txf) : 0.0f;
            float wx1 = (ix0 + 1 >= 0 && ix0 + 1 < W_) ? txf : 0.0f;
            int x0c = min(max(ix0, 0), W_ - 1);
            int x1c = min(max(ix0 + 1, 0), W_ - 1);
            float rw = wsum * __ldg(&dubase[w0 + gw1]) + rho0;
            float sv = wx0 * (S_s[gw1 * 200 + x0c] + dvyb_s[x0c])
                     + wx1 * (S_s[gw1 * 200 + x1c] + dvyb_s[x1c])
                     + (wx0 + wx1) * rw;
            outb[gd1 * HW_ + w0 + gw1] = sv * 0.015625f;
        }
        dsp0 = nd0; dsp1 = nd1;
    }
}

extern "C" void kernel_launch(void* const* d_in, const int* in_sizes, int n_in,
                              void* d_out, int out_size) {
    const float* x  = (const float*)d_in[0];
    const float* y  = (const float*)d_in[1];
    const float* d1 = (const float*)d_in[2];
    const float* d2 = (const float*)d_in[3];
    int wbase = (in_sizes[4] == 1) ? 5 : 4;
    const float* qw = (const float*)d_in[wbase + 0];
    const float* qb = (const float*)d_in[wbase + 1];
    const float* kw = (const float*)d_in[wbase + 2];
    const float* kb = (const float*)d_in[wbase + 3];
    float* out = (float*)d_out;

    cudaFuncSetAttribute(z_kernel,
                         cudaFuncAttributeMaxDynamicSharedMemorySize, 51200);
    cudaFuncSetAttribute(cost_kernel,
                         cudaFuncAttributeMaxDynamicSharedMemorySize, 69120);

    prep_kernel<<<17, 256>>>(qw, qb, kw, kb);
    z_kernel<<<dim3(H_, B_, 2), 256, 51200>>>(x, y);
    cost_kernel<<<dim3(H_, B_, 2), 256, 69120>>>(x, y, d1, d2, out);
}